// round 2
// baseline (speedup 1.0000x reference)
#include <cuda_runtime.h>
#include <cstdint>

// ---------------- problem constants ----------------
#define BATCH 8
#define IMH 80
#define IMW 80
#define C_ 768
#define NH 12
#define HD 64
#define WIN 14
#define NWIN 6            // windows per side (84/14)
#define NWINS 36          // NWIN*NWIN
#define NW 196            // tokens per window
#define NTOK (IMH*IMW)    // 6400
#define MROWS (BATCH*NTOK) // 51200

// scratch (allowed: __device__ globals, no cudaMalloc)
__device__ float g_qkv[(size_t)MROWS * 3 * C_];   // [M, 2304]
__device__ float g_attn[(size_t)MROWS * C_];      // [M, 768]

__device__ __forceinline__ uint32_t f2tf32(float f) {
    uint32_t r;
    asm("cvt.rna.tf32.f32 %0, %1;" : "=r"(r) : "f"(f));
    return r;
}

// ---------------- tf32 mma GEMM: C[M,N] = A[M,K] @ B[K,N] (+bias) ----------------
// BM=128, BN=128, BK=16; 256 threads, 8 warps in 2x4 grid; warp tile 64x32
// assumes M%128==0, N%128==0, K%16==0 (true for all our shapes)
__global__ void __launch_bounds__(256) gemm_tf32(const float* __restrict__ A,
                                                 const float* __restrict__ B,
                                                 const float* __restrict__ bias,
                                                 float* __restrict__ C,
                                                 int M, int N, int K)
{
    __shared__ uint32_t As[16][128 + 4];  // [k][m]
    __shared__ uint32_t Bs[16][128 + 4];  // [k][n]

    const int tid  = threadIdx.x;
    const int warp = tid >> 5;
    const int lane = tid & 31;
    const int wm = warp & 1;        // 0..1
    const int wn = warp >> 1;       // 0..3
    const int tg = lane >> 2;       // group id 0..7
    const int tc = lane & 3;        // thread-in-group 0..3

    const int bm = blockIdx.y * 128;
    const int bn = blockIdx.x * 128;

    float acc[4][4][4];
#pragma unroll
    for (int i = 0; i < 4; i++)
#pragma unroll
        for (int j = 0; j < 4; j++)
#pragma unroll
            for (int r = 0; r < 4; r++) acc[i][j][r] = 0.f;

    for (int k0 = 0; k0 < K; k0 += 16) {
        // A tile: 128 rows x 16 k (512 float4 loads)
#pragma unroll
        for (int i = 0; i < 2; i++) {
            int item = tid + 256 * i;
            int row = item >> 2;
            int c4  = item & 3;
            float4 v = *reinterpret_cast<const float4*>(&A[(size_t)(bm + row) * K + k0 + c4 * 4]);
            As[c4 * 4 + 0][row] = f2tf32(v.x);
            As[c4 * 4 + 1][row] = f2tf32(v.y);
            As[c4 * 4 + 2][row] = f2tf32(v.z);
            As[c4 * 4 + 3][row] = f2tf32(v.w);
        }
        // B tile: 16 k x 128 n
#pragma unroll
        for (int i = 0; i < 2; i++) {
            int item = tid + 256 * i;
            int row = item >> 5;
            int c4  = item & 31;
            float4 v = *reinterpret_cast<const float4*>(&B[(size_t)(k0 + row) * N + bn + c4 * 4]);
            Bs[row][c4 * 4 + 0] = f2tf32(v.x);
            Bs[row][c4 * 4 + 1] = f2tf32(v.y);
            Bs[row][c4 * 4 + 2] = f2tf32(v.z);
            Bs[row][c4 * 4 + 3] = f2tf32(v.w);
        }
        __syncthreads();

#pragma unroll
        for (int ks = 0; ks < 16; ks += 8) {
            uint32_t af[4][4], bf[4][2];
#pragma unroll
            for (int mi = 0; mi < 4; mi++) {
                int r0 = wm * 64 + mi * 16 + tg;
                af[mi][0] = As[ks + tc][r0];
                af[mi][1] = As[ks + tc][r0 + 8];
                af[mi][2] = As[ks + tc + 4][r0];
                af[mi][3] = As[ks + tc + 4][r0 + 8];
            }
#pragma unroll
            for (int ni = 0; ni < 4; ni++) {
                int c0 = wn * 32 + ni * 8 + tg;
                bf[ni][0] = Bs[ks + tc][c0];
                bf[ni][1] = Bs[ks + tc + 4][c0];
            }
#pragma unroll
            for (int mi = 0; mi < 4; mi++)
#pragma unroll
                for (int ni = 0; ni < 4; ni++)
                    asm volatile(
                        "mma.sync.aligned.m16n8k8.row.col.f32.tf32.tf32.f32 "
                        "{%0,%1,%2,%3}, {%4,%5,%6,%7}, {%8,%9}, {%0,%1,%2,%3};"
                        : "+f"(acc[mi][ni][0]), "+f"(acc[mi][ni][1]),
                          "+f"(acc[mi][ni][2]), "+f"(acc[mi][ni][3])
                        : "r"(af[mi][0]), "r"(af[mi][1]), "r"(af[mi][2]), "r"(af[mi][3]),
                          "r"(bf[ni][0]), "r"(bf[ni][1]));
        }
        __syncthreads();
    }

    // epilogue: c0/c1 at (row, 2tc/2tc+1), c2/c3 at (row+8, same)
#pragma unroll
    for (int mi = 0; mi < 4; mi++) {
        int row = bm + wm * 64 + mi * 16 + tg;
#pragma unroll
        for (int ni = 0; ni < 4; ni++) {
            int col = bn + wn * 32 + ni * 8 + tc * 2;
            float b0 = bias ? bias[col]     : 0.f;
            float b1 = bias ? bias[col + 1] : 0.f;
            float2 v0 = make_float2(acc[mi][ni][0] + b0, acc[mi][ni][1] + b1);
            float2 v1 = make_float2(acc[mi][ni][2] + b0, acc[mi][ni][3] + b1);
            *reinterpret_cast<float2*>(&C[(size_t)row * N + col])       = v0;
            *reinterpret_cast<float2*>(&C[(size_t)(row + 8) * N + col]) = v1;
        }
    }
}

// ---------------- windowed attention (fp32 SIMT, register-blocked) ----------------
// one CTA per (b, window, head); 256 threads = 8 warps; each warp handles 4 q rows/iter
#define QKS 65   // Q/K smem row stride (floats)
#define VST 66   // V smem row stride (floats, keeps float2 alignment)

#define ATTN_SMEM_FLOATS (2 * NW * QKS + NW * VST + 8 * NW * 4)
#define ATTN_SMEM_BYTES  (ATTN_SMEM_FLOATS * 4)

__global__ void __launch_bounds__(256) attn_kernel(const float* __restrict__ qkv,
                                                   float* __restrict__ out)
{
    extern __shared__ float sm[];
    float* Qs = sm;                 // [196][65]
    float* Ks = Qs + NW * QKS;      // [196][65]
    float* Vs = Ks + NW * QKS;      // [196][66]
    float* Ps = Vs + NW * VST;      // [8][196][4]

    const int bid = blockIdx.x;
    const int h = bid % NH;
    const int l = (bid / NH) % NWINS;
    const int b = bid / (NH * NWINS);
    const int wh = l / NWIN, ww = l % NWIN;

    const int tid  = threadIdx.x;
    const int warp = tid >> 5;
    const int lane = tid & 31;

    // gather window tiles (zero-fill padded positions: matches reference's zero-pad)
    for (int idx = tid; idx < NW * HD; idx += 256) {
        int n = idx >> 6, d = idx & 63;
        int gh = wh * WIN + (n / WIN);
        int gw = ww * WIN + (n % WIN);
        float q = 0.f, k = 0.f, v = 0.f;
        if (gh < IMH && gw < IMW) {
            size_t off = (size_t)(b * NTOK + gh * IMW + gw) * (3 * C_) + h * HD + d;
            q = qkv[off];
            k = qkv[off + C_];
            v = qkv[off + 2 * C_];
        }
        Qs[n * QKS + d] = q;
        Ks[n * QKS + d] = k;
        Vs[n * VST + d] = v;
    }
    __syncthreads();

    const float scale = 0.125f;  // hd^-0.5, hd=64
    float* Pw = Ps + warp * NW * 4;
    const int jmax = (lane < NW - 192) ? 7 : 6;  // j = lane + 32*jj < 196

    for (int it = 0; it < 7; it++) {
        int base = it * 32 + warp * 4;
        if (base >= NW) continue;

        // ---- scores: 4 rows x 7 j's per lane ----
        float s[4][7];
#pragma unroll
        for (int r = 0; r < 4; r++)
#pragma unroll
            for (int jj = 0; jj < 7; jj++) s[r][jj] = 0.f;

        const float* q0p = &Qs[(base + 0) * QKS];
        const float* q1p = &Qs[(base + 1) * QKS];
        const float* q2p = &Qs[(base + 2) * QKS];
        const float* q3p = &Qs[(base + 3) * QKS];

#pragma unroll 4
        for (int kk = 0; kk < HD; kk++) {
            float q0 = q0p[kk], q1 = q1p[kk], q2 = q2p[kk], q3 = q3p[kk];
#pragma unroll
            for (int jj = 0; jj < 7; jj++) {
                if (jj < jmax) {
                    float kv = Ks[(lane + 32 * jj) * QKS + kk];
                    s[0][jj] += q0 * kv;
                    s[1][jj] += q1 * kv;
                    s[2][jj] += q2 * kv;
                    s[3][jj] += q3 * kv;
                }
            }
        }

        // ---- softmax per row, write P (transposed [j][r] for float4 loads) ----
#pragma unroll
        for (int r = 0; r < 4; r++) {
            float m = -1e30f;
#pragma unroll
            for (int jj = 0; jj < 7; jj++)
                if (jj < jmax) m = fmaxf(m, s[r][jj] * scale);
#pragma unroll
            for (int o = 16; o > 0; o >>= 1)
                m = fmaxf(m, __shfl_xor_sync(0xffffffffu, m, o));
            float sum = 0.f;
            float e[7];
#pragma unroll
            for (int jj = 0; jj < 7; jj++) {
                e[jj] = (jj < jmax) ? __expf(s[r][jj] * scale - m) : 0.f;
                sum += e[jj];
            }
#pragma unroll
            for (int o = 16; o > 0; o >>= 1)
                sum += __shfl_xor_sync(0xffffffffu, sum, o);
            float inv = 1.f / sum;
#pragma unroll
            for (int jj = 0; jj < 7; jj++)
                if (jj < jmax) Pw[(lane + 32 * jj) * 4 + r] = e[jj] * inv;
        }
        __syncwarp();

        // ---- P @ V: lane owns d = {2*lane, 2*lane+1} ----
        float2 a0 = make_float2(0.f, 0.f), a1 = a0, a2 = a0, a3 = a0;
        const float* vbase = &Vs[2 * lane];
        for (int j = 0; j < NW; j++) {
            float4 p  = *reinterpret_cast<const float4*>(&Pw[j * 4]);
            float2 v2 = *reinterpret_cast<const float2*>(&vbase[j * VST]);
            a0.x += p.x * v2.x; a0.y += p.x * v2.y;
            a1.x += p.y * v2.x; a1.y += p.y * v2.y;
            a2.x += p.z * v2.x; a2.y += p.z * v2.y;
            a3.x += p.w * v2.x; a3.y += p.w * v2.y;
        }
        __syncwarp();  // Pw reused next iteration

        float2 av[4] = {a0, a1, a2, a3};
#pragma unroll
        for (int r = 0; r < 4; r++) {
            int n = base + r;
            int gh = wh * WIN + n / WIN;
            int gw = ww * WIN + n % WIN;
            if (gh < IMH && gw < IMW) {  // crop padded rows
                size_t off = (size_t)(b * NTOK + gh * IMW + gw) * C_ + h * HD + 2 * lane;
                *reinterpret_cast<float2*>(&out[off]) = av[r];
            }
        }
    }
}

// ---------------- launcher ----------------
extern "C" void kernel_launch(void* const* d_in, const int* in_sizes, int n_in,
                              void* d_out, int out_size)
{
    (void)in_sizes; (void)n_in; (void)out_size;
    const float* x     = (const float*)d_in[0];
    const float* Wqkv  = (const float*)d_in[1];
    const float* Wproj = (const float*)d_in[2];
    const float* bproj = (const float*)d_in[3];
    float* out = (float*)d_out;

    float* qkv  = nullptr;
    float* attn = nullptr;
    cudaGetSymbolAddress((void**)&qkv,  g_qkv);
    cudaGetSymbolAddress((void**)&attn, g_attn);

    cudaFuncSetAttribute(attn_kernel, cudaFuncAttributeMaxDynamicSharedMemorySize,
                         ATTN_SMEM_BYTES);

    // 1) qkv = x @ Wqkv           [51200,768] x [768,2304]
    {
        dim3 grid(3 * C_ / 128, MROWS / 128);
        gemm_tf32<<<grid, 256>>>(x, Wqkv, nullptr, qkv, MROWS, 3 * C_, C_);
    }
    // 2) windowed attention       3456 CTAs
    {
        dim3 grid(BATCH * NWINS * NH);
        attn_kernel<<<grid, 256, ATTN_SMEM_BYTES>>>(qkv, attn);
    }
    // 3) out = attn @ Wproj + b   [51200,768] x [768,768]
    {
        dim3 grid(C_ / 128, MROWS / 128);
        gemm_tf32<<<grid, 256>>>(attn, Wproj, bproj, out, MROWS, C_, C_);
    }
}

// round 3
// speedup vs baseline: 1.3641x; 1.3641x over previous
#include <cuda_runtime.h>
#include <cstdint>

// ---------------- problem constants ----------------
#define BATCH 8
#define IMH 80
#define IMW 80
#define C_ 768
#define NH 12
#define HD 64
#define WIN 14
#define NWIN 6
#define NWINS 36
#define NW 196
#define NTOK (IMH*IMW)
#define MROWS (BATCH*NTOK)   // 51200

// scratch
__device__ float g_qkv[(size_t)MROWS * 3 * C_];
__device__ float g_attn[(size_t)MROWS * C_];
__device__ float g_x32[(size_t)MROWS * C_];
__device__ float g_wqkvT[(size_t)3 * C_ * C_];   // [2304][768]
__device__ float g_wprojT[(size_t)C_ * C_];      // [768][768]

__device__ __forceinline__ float f2tf32f(float f) {
    uint32_t r;
    asm("cvt.rna.tf32.f32 %0, %1;" : "=r"(r) : "f"(f));
    return __uint_as_float(r);
}

// ---------------- prepass: elementwise cvt.rna ----------------
__global__ void cvt_kernel(const float* __restrict__ in, float* __restrict__ out, int n4)
{
    int i = blockIdx.x * blockDim.x + threadIdx.x;
    for (; i < n4; i += gridDim.x * blockDim.x) {
        float4 v = reinterpret_cast<const float4*>(in)[i];
        v.x = f2tf32f(v.x); v.y = f2tf32f(v.y);
        v.z = f2tf32f(v.z); v.w = f2tf32f(v.w);
        reinterpret_cast<float4*>(out)[i] = v;
    }
}

// ---------------- prepass: transpose + cvt.rna  (in [R][Cc] -> out [Cc][R]) ----------------
__global__ void transpose_cvt(const float* __restrict__ in, float* __restrict__ out,
                              int R, int Cc)
{
    __shared__ float tile[32][33];
    int x = blockIdx.x * 32 + threadIdx.x;   // col in input
    int y0 = blockIdx.y * 32;                // row block in input
#pragma unroll
    for (int j = 0; j < 32; j += 8)
        tile[threadIdx.y + j][threadIdx.x] = in[(size_t)(y0 + threadIdx.y + j) * Cc + x];
    __syncthreads();
    int ox = blockIdx.y * 32 + threadIdx.x;  // col in output (= input row)
    int oy0 = blockIdx.x * 32;               // row block in output (= input col)
#pragma unroll
    for (int j = 0; j < 32; j += 8)
        out[(size_t)(oy0 + threadIdx.y + j) * R + ox] =
            f2tf32f(tile[threadIdx.x][threadIdx.y + j]);
}

// ---------------- tf32 mma GEMM, cp.async + ldmatrix ----------------
// C[M,N] = A[M,K] @ Bt[N,K]^T (+bias).  A, Bt already tf32-rounded.
// BM=BN=128, BK=32, 2-stage cp.async pipeline, 8 warps (2x4), warp tile 64x32.
#define BK 32
#define LDT 36                        // padded row stride (floats): conflict-free for ldmatrix
#define TILE_FLOATS (128 * LDT)       // 4608 per matrix
#define STAGE_FLOATS (2 * TILE_FLOATS)
#define STAGE_BYTES (STAGE_FLOATS * 4)        // 36864
#define GEMM_SMEM_BYTES (2 * STAGE_BYTES)     // 73728

__device__ __forceinline__ void cp_async16(uint32_t smem_addr, const float* gptr) {
    asm volatile("cp.async.cg.shared.global [%0], [%1], 16;"
                 :: "r"(smem_addr), "l"(gptr));
}

__global__ void __launch_bounds__(256, 2) gemm_tf32_async(
    const float* __restrict__ A, const float* __restrict__ Bt,
    const float* __restrict__ bias, float* __restrict__ C,
    int M, int N, int K)
{
    extern __shared__ float smem[];
    const uint32_t smem_base = (uint32_t)__cvta_generic_to_shared(smem);

    const int tid  = threadIdx.x;
    const int warp = tid >> 5;
    const int lane = tid & 31;
    const int wm = warp & 1;
    const int wn = warp >> 1;
    const int bm = blockIdx.y * 128;
    const int bn = blockIdx.x * 128;

    // ldmatrix per-lane address components
    const int aRow = wm * 64 + (lane & 15);
    const int aCol = (lane >> 4) * 4;                          // 0 or 4
    const int bRow = wn * 32 + (lane & 7) + ((lane & 16) ? 8 : 0);
    const int bCol = (lane & 8) ? 4 : 0;

    float acc[4][4][4];
#pragma unroll
    for (int i = 0; i < 4; i++)
#pragma unroll
        for (int j = 0; j < 4; j++)
#pragma unroll
            for (int r = 0; r < 4; r++) acc[i][j][r] = 0.f;

    // cp.async staging: per thread 4 A-chunks + 4 B-chunks of 16B per stage
    const int crow = tid >> 3;          // base row for chunk mapping (c>>3 with c=tid+256i -> rows interleave)
    // we map chunk c = tid + 256*i: row = c>>3, kc = (c&7)*4
    const int NT = K / BK;

    auto issue_stage = [&](int t, int s) {
        const float* Ag = A + (size_t)bm * K + t * BK;
        const float* Bg = Bt + (size_t)bn * K + t * BK;
        uint32_t as = smem_base + s * STAGE_BYTES;
        uint32_t bs = as + TILE_FLOATS * 4;
#pragma unroll
        for (int i = 0; i < 4; i++) {
            int c   = tid + 256 * i;
            int row = c >> 3;
            int kc  = (c & 7) * 4;
            uint32_t doff = (uint32_t)(row * LDT + kc) * 4;
            cp_async16(as + doff, Ag + (size_t)row * K + kc);
            cp_async16(bs + doff, Bg + (size_t)row * K + kc);
        }
        asm volatile("cp.async.commit_group;");
    };
    (void)crow;

    issue_stage(0, 0);

    for (int t = 0; t < NT; t++) {
        int s = t & 1;
        if (t + 1 < NT) {
            issue_stage(t + 1, (t + 1) & 1);
            asm volatile("cp.async.wait_group 1;");
        } else {
            asm volatile("cp.async.wait_group 0;");
        }
        __syncthreads();

        uint32_t as = smem_base + s * STAGE_BYTES;
        uint32_t bs = as + TILE_FLOATS * 4;

#pragma unroll
        for (int ks = 0; ks < 4; ks++) {
            uint32_t af[4][4];
#pragma unroll
            for (int mi = 0; mi < 4; mi++) {
                uint32_t addr = as + (uint32_t)((aRow + mi * 16) * LDT + aCol + ks * 8) * 4;
                asm volatile("ldmatrix.sync.aligned.m8n8.x4.shared.b16 {%0,%1,%2,%3}, [%4];"
                             : "=r"(af[mi][0]), "=r"(af[mi][1]),
                               "=r"(af[mi][2]), "=r"(af[mi][3])
                             : "r"(addr));
            }
            uint32_t bf[2][4];
#pragma unroll
            for (int np = 0; np < 2; np++) {
                uint32_t addr = bs + (uint32_t)((bRow + np * 16) * LDT + bCol + ks * 8) * 4;
                asm volatile("ldmatrix.sync.aligned.m8n8.x4.shared.b16 {%0,%1,%2,%3}, [%4];"
                             : "=r"(bf[np][0]), "=r"(bf[np][1]),
                               "=r"(bf[np][2]), "=r"(bf[np][3])
                             : "r"(addr));
            }
#pragma unroll
            for (int mi = 0; mi < 4; mi++) {
#pragma unroll
                for (int np = 0; np < 2; np++) {
                    asm volatile(
                        "mma.sync.aligned.m16n8k8.row.col.f32.tf32.tf32.f32 "
                        "{%0,%1,%2,%3}, {%4,%5,%6,%7}, {%8,%9}, {%0,%1,%2,%3};"
                        : "+f"(acc[mi][2*np][0]), "+f"(acc[mi][2*np][1]),
                          "+f"(acc[mi][2*np][2]), "+f"(acc[mi][2*np][3])
                        : "r"(af[mi][0]), "r"(af[mi][1]), "r"(af[mi][2]), "r"(af[mi][3]),
                          "r"(bf[np][0]), "r"(bf[np][1]));
                    asm volatile(
                        "mma.sync.aligned.m16n8k8.row.col.f32.tf32.tf32.f32 "
                        "{%0,%1,%2,%3}, {%4,%5,%6,%7}, {%8,%9}, {%0,%1,%2,%3};"
                        : "+f"(acc[mi][2*np+1][0]), "+f"(acc[mi][2*np+1][1]),
                          "+f"(acc[mi][2*np+1][2]), "+f"(acc[mi][2*np+1][3])
                        : "r"(af[mi][0]), "r"(af[mi][1]), "r"(af[mi][2]), "r"(af[mi][3]),
                          "r"(bf[np][2]), "r"(bf[np][3]));
                }
            }
        }
        __syncthreads();
    }

    const int tg = lane >> 2;
    const int tc = lane & 3;
#pragma unroll
    for (int mi = 0; mi < 4; mi++) {
        int row = bm + wm * 64 + mi * 16 + tg;
#pragma unroll
        for (int ni = 0; ni < 4; ni++) {
            int col = bn + wn * 32 + ni * 8 + tc * 2;
            float b0 = bias ? bias[col]     : 0.f;
            float b1 = bias ? bias[col + 1] : 0.f;
            float2 v0 = make_float2(acc[mi][ni][0] + b0, acc[mi][ni][1] + b1);
            float2 v1 = make_float2(acc[mi][ni][2] + b0, acc[mi][ni][3] + b1);
            *reinterpret_cast<float2*>(&C[(size_t)row * N + col])       = v0;
            *reinterpret_cast<float2*>(&C[(size_t)(row + 8) * N + col]) = v1;
        }
    }
}

// ---------------- windowed attention (fp32 SIMT, register-blocked) ----------------
#define QKS 65
#define VST 66
#define ATTN_SMEM_FLOATS (2 * NW * QKS + NW * VST + 8 * NW * 4)
#define ATTN_SMEM_BYTES  (ATTN_SMEM_FLOATS * 4)

__global__ void __launch_bounds__(256) attn_kernel(const float* __restrict__ qkv,
                                                   float* __restrict__ out)
{
    extern __shared__ float sm[];
    float* Qs = sm;
    float* Ks = Qs + NW * QKS;
    float* Vs = Ks + NW * QKS;
    float* Ps = Vs + NW * VST;

    const int bid = blockIdx.x;
    const int h = bid % NH;
    const int l = (bid / NH) % NWINS;
    const int b = bid / (NH * NWINS);
    const int wh = l / NWIN, ww = l % NWIN;

    const int tid  = threadIdx.x;
    const int warp = tid >> 5;
    const int lane = tid & 31;

    for (int idx = tid; idx < NW * HD; idx += 256) {
        int n = idx >> 6, d = idx & 63;
        int gh = wh * WIN + (n / WIN);
        int gw = ww * WIN + (n % WIN);
        float q = 0.f, k = 0.f, v = 0.f;
        if (gh < IMH && gw < IMW) {
            size_t off = (size_t)(b * NTOK + gh * IMW + gw) * (3 * C_) + h * HD + d;
            q = qkv[off];
            k = qkv[off + C_];
            v = qkv[off + 2 * C_];
        }
        Qs[n * QKS + d] = q;
        Ks[n * QKS + d] = k;
        Vs[n * VST + d] = v;
    }
    __syncthreads();

    const float scale = 0.125f;
    float* Pw = Ps + warp * NW * 4;
    const int jmax = (lane < NW - 192) ? 7 : 6;

    for (int it = 0; it < 7; it++) {
        int base = it * 32 + warp * 4;
        if (base >= NW) continue;

        float s[4][7];
#pragma unroll
        for (int r = 0; r < 4; r++)
#pragma unroll
            for (int jj = 0; jj < 7; jj++) s[r][jj] = 0.f;

        const float* q0p = &Qs[(base + 0) * QKS];
        const float* q1p = &Qs[(base + 1) * QKS];
        const float* q2p = &Qs[(base + 2) * QKS];
        const float* q3p = &Qs[(base + 3) * QKS];

#pragma unroll 4
        for (int kk = 0; kk < HD; kk++) {
            float q0 = q0p[kk], q1 = q1p[kk], q2 = q2p[kk], q3 = q3p[kk];
#pragma unroll
            for (int jj = 0; jj < 7; jj++) {
                if (jj < jmax) {
                    float kv = Ks[(lane + 32 * jj) * QKS + kk];
                    s[0][jj] += q0 * kv;
                    s[1][jj] += q1 * kv;
                    s[2][jj] += q2 * kv;
                    s[3][jj] += q3 * kv;
                }
            }
        }

#pragma unroll
        for (int r = 0; r < 4; r++) {
            float m = -1e30f;
#pragma unroll
            for (int jj = 0; jj < 7; jj++)
                if (jj < jmax) m = fmaxf(m, s[r][jj] * scale);
#pragma unroll
            for (int o = 16; o > 0; o >>= 1)
                m = fmaxf(m, __shfl_xor_sync(0xffffffffu, m, o));
            float sum = 0.f;
            float e[7];
#pragma unroll
            for (int jj = 0; jj < 7; jj++) {
                e[jj] = (jj < jmax) ? __expf(s[r][jj] * scale - m) : 0.f;
                sum += e[jj];
            }
#pragma unroll
            for (int o = 16; o > 0; o >>= 1)
                sum += __shfl_xor_sync(0xffffffffu, sum, o);
            float inv = 1.f / sum;
#pragma unroll
            for (int jj = 0; jj < 7; jj++)
                if (jj < jmax) Pw[(lane + 32 * jj) * 4 + r] = e[jj] * inv;
        }
        __syncwarp();

        float2 a0 = make_float2(0.f, 0.f), a1 = a0, a2 = a0, a3 = a0;
        const float* vbase = &Vs[2 * lane];
        for (int j = 0; j < NW; j++) {
            float4 p  = *reinterpret_cast<const float4*>(&Pw[j * 4]);
            float2 v2 = *reinterpret_cast<const float2*>(&vbase[j * VST]);
            a0.x += p.x * v2.x; a0.y += p.x * v2.y;
            a1.x += p.y * v2.x; a1.y += p.y * v2.y;
            a2.x += p.z * v2.x; a2.y += p.z * v2.y;
            a3.x += p.w * v2.x; a3.y += p.w * v2.y;
        }
        __syncwarp();

        float2 av[4] = {a0, a1, a2, a3};
#pragma unroll
        for (int r = 0; r < 4; r++) {
            int n = base + r;
            int gh = wh * WIN + n / WIN;
            int gw = ww * WIN + n % WIN;
            if (gh < IMH && gw < IMW) {
                size_t off = (size_t)(b * NTOK + gh * IMW + gw) * C_ + h * HD + 2 * lane;
                // write tf32-rounded so GEMM2 consumes clean tf32 (numerics match prior round)
                float2 o2 = make_float2(f2tf32f(av[r].x), f2tf32f(av[r].y));
                *reinterpret_cast<float2*>(&out[off]) = o2;
            }
        }
    }
}

// ---------------- launcher ----------------
extern "C" void kernel_launch(void* const* d_in, const int* in_sizes, int n_in,
                              void* d_out, int out_size)
{
    (void)in_sizes; (void)n_in; (void)out_size;
    const float* x     = (const float*)d_in[0];
    const float* Wqkv  = (const float*)d_in[1];
    const float* Wproj = (const float*)d_in[2];
    const float* bproj = (const float*)d_in[3];
    float* out = (float*)d_out;

    float *qkv, *attn, *x32, *wqkvT, *wprojT;
    cudaGetSymbolAddress((void**)&qkv,    g_qkv);
    cudaGetSymbolAddress((void**)&attn,   g_attn);
    cudaGetSymbolAddress((void**)&x32,    g_x32);
    cudaGetSymbolAddress((void**)&wqkvT,  g_wqkvT);
    cudaGetSymbolAddress((void**)&wprojT, g_wprojT);

    cudaFuncSetAttribute(attn_kernel, cudaFuncAttributeMaxDynamicSharedMemorySize,
                         ATTN_SMEM_BYTES);
    cudaFuncSetAttribute(gemm_tf32_async, cudaFuncAttributeMaxDynamicSharedMemorySize,
                         GEMM_SMEM_BYTES);

    // prepass: tf32-round inputs / transpose weights
    cvt_kernel<<<1184, 256>>>(x, x32, MROWS * C_ / 4);
    {
        dim3 g(3 * C_ / 32, C_ / 32), blk(32, 8);
        transpose_cvt<<<g, blk>>>(Wqkv, wqkvT, C_, 3 * C_);
    }
    {
        dim3 g(C_ / 32, C_ / 32), blk(32, 8);
        transpose_cvt<<<g, blk>>>(Wproj, wprojT, C_, C_);
    }

    // 1) qkv = x @ Wqkv
    {
        dim3 grid(3 * C_ / 128, MROWS / 128);
        gemm_tf32_async<<<grid, 256, GEMM_SMEM_BYTES>>>(x32, wqkvT, nullptr, qkv,
                                                        MROWS, 3 * C_, C_);
    }
    // 2) windowed attention
    {
        dim3 grid(BATCH * NWINS * NH);
        attn_kernel<<<grid, 256, ATTN_SMEM_BYTES>>>(qkv, attn);
    }
    // 3) out = attn @ Wproj + bproj
    {
        dim3 grid(C_ / 128, MROWS / 128);
        gemm_tf32_async<<<grid, 256, GEMM_SMEM_BYTES>>>(attn, wprojT, bproj, out,
                                                        MROWS, C_, C_);
    }
}